// round 7
// baseline (speedup 1.0000x reference)
#include <cuda_runtime.h>

// SpikeLoss: loss = 0.5 * sum( (outputs - psp(target))^2 )
// psp: syn_t = 0.8*syn_{t-1} + x_t ; y_t = 0.2*syn_t
// [32,256,4,4,100], T contiguous -> 131072 rows of 100 floats.
//
// One WARP per row; rows processed in PAIRS with all 4 float4 loads hoisted
// (MLP>=4, two independent Kogge-Stone chains interleave to hide SHFL lat).
// Lane l holds timesteps [4l,4l+3]; lanes 0..24 active. No smem/barriers in
// the hot path. Fused deterministic last-block-done reduction (1 launch).

#define T_STEPS   100
#define THREADS   256
#define WARPS_PB  (THREADS / 32)        // 8
#define ROWS_PER_WARP 8
#define NBLOCKS   2048                  // 131072 / (8*8)

#define A1  0.8f
#define A2  0.64f
#define A3  0.512f
#define A4  0.4096f
#define A8  0.16777216f
#define A16 0.028147497671065608f
#define A32 0.0007922816251426434f
#define A64 6.277101735386681e-07f
#define INV_TAU 0.2f

__device__ float    g_partials[NBLOCKS];
__device__ unsigned g_count = 0;

__device__ __forceinline__ float row_scan_sq(float4 x, float4 o, int lane, bool active)
{
    // Intra-lane scan of 4 timesteps
    float p0 = x.x;
    float p1 = fmaf(A1, p0, x.y);
    float p2 = fmaf(A1, p1, x.z);
    float p3 = fmaf(A1, p2, x.w);

    // Kogge-Stone inclusive scan over segment totals (ratio 0.8^4)
    float T = p3, u;
    u = __shfl_up_sync(0xFFFFFFFFu, T, 1);  if (lane >= 1)  T = fmaf(A4,  u, T);
    u = __shfl_up_sync(0xFFFFFFFFu, T, 2);  if (lane >= 2)  T = fmaf(A8,  u, T);
    u = __shfl_up_sync(0xFFFFFFFFu, T, 4);  if (lane >= 4)  T = fmaf(A16, u, T);
    u = __shfl_up_sync(0xFFFFFFFFu, T, 8);  if (lane >= 8)  T = fmaf(A32, u, T);
    u = __shfl_up_sync(0xFFFFFFFFu, T, 16); if (lane >= 16) T = fmaf(A64, u, T);

    // Exclusive carry entering this lane's segment
    float C = __shfl_up_sync(0xFFFFFFFFu, T, 1);
    if (lane == 0) C = 0.0f;

    // Reconstruct syn, diff vs outputs, sum of squares
    float s0 = fmaf(A1, C, p0);
    float s1 = fmaf(A2, C, p1);
    float s2 = fmaf(A3, C, p2);
    float s3 = fmaf(A4, C, p3);

    float r = 0.0f;
    if (active) {
        float d0 = fmaf(-INV_TAU, s0, o.x);
        float d1 = fmaf(-INV_TAU, s1, o.y);
        float d2 = fmaf(-INV_TAU, s2, o.z);
        float d3 = fmaf(-INV_TAU, s3, o.w);
        r = d0 * d0;
        r = fmaf(d1, d1, r);
        r = fmaf(d2, d2, r);
        r = fmaf(d3, d3, r);
    }
    return r;
}

__global__ void __launch_bounds__(THREADS)
spike_loss_warpscan(const float* __restrict__ outputs,
                    const float* __restrict__ target,
                    float* __restrict__ out,
                    int n_blocks)
{
    __shared__ float s_warp[WARPS_PB];
    __shared__ int   s_is_last;

    const int tid  = threadIdx.x;
    const int lane = tid & 31;
    const int wid  = tid >> 5;
    const int gwarp = blockIdx.x * WARPS_PB + wid;
    const bool active = (lane < 25);

    const float4* __restrict__ t4 = (const float4*)target;
    const float4* __restrict__ o4 = (const float4*)outputs;

    float acc = 0.0f;

    #pragma unroll 2
    for (int i = 0; i < ROWS_PER_WARP / 2; i++) {
        const size_t base0 = ((size_t)gwarp * ROWS_PER_WARP + 2 * i) * 25;
        const size_t base1 = base0 + 25;

        float4 x0 = make_float4(0.f, 0.f, 0.f, 0.f);
        float4 o0 = x0, x1 = x0, o1 = x0;
        if (active) {
            x0 = __ldcs(&t4[base0 + lane]);
            x1 = __ldcs(&t4[base1 + lane]);
            o0 = __ldcs(&o4[base0 + lane]);
            o1 = __ldcs(&o4[base1 + lane]);
        }

        // Two independent scan chains — scheduler interleaves them
        acc += row_scan_sq(x0, o0, lane, active);
        acc += row_scan_sq(x1, o1, lane, active);
    }

    // ---- Block reduction (deterministic) ----
    #pragma unroll
    for (int off = 16; off > 0; off >>= 1)
        acc += __shfl_down_sync(0xFFFFFFFFu, acc, off);
    if (lane == 0) s_warp[wid] = acc;
    __syncthreads();

    if (tid == 0) {
        float v = 0.0f;
        #pragma unroll
        for (int w = 0; w < WARPS_PB; w++) v += s_warp[w];
        g_partials[blockIdx.x] = v;
        __threadfence();
        unsigned old = atomicAdd(&g_count, 1u);
        s_is_last = (old == (unsigned)(n_blocks - 1));
    }
    __syncthreads();

    // ---- Last block: deterministic final reduce ----
    if (s_is_last) {
        float v = 0.0f;
        #pragma unroll
        for (int j = 0; j < NBLOCKS / THREADS; j++) {      // fixed order
            int idx = tid + j * THREADS;
            if (idx < n_blocks) v += g_partials[idx];
        }
        #pragma unroll
        for (int off = 16; off > 0; off >>= 1)
            v += __shfl_down_sync(0xFFFFFFFFu, v, off);
        if (lane == 0) s_warp[wid] = v;
        __syncthreads();
        if (tid == 0) {
            float r = 0.0f;
            #pragma unroll
            for (int w = 0; w < WARPS_PB; w++) r += s_warp[w];
            out[0] = 0.5f * r;
            g_count = 0;   // reset for next graph replay
        }
    }
}

extern "C" void kernel_launch(void* const* d_in, const int* in_sizes, int n_in,
                              void* d_out, int out_size)
{
    const float* outputs = (const float*)d_in[0];
    const float* target  = (const float*)d_in[1];
    float* out = (float*)d_out;

    int n_rows = in_sizes[0] / T_STEPS;                    // 131072
    int blocks = n_rows / (WARPS_PB * ROWS_PER_WARP);      // 2048

    spike_loss_warpscan<<<blocks, THREADS>>>(outputs, target, out, blocks);
}

// round 17
// speedup vs baseline: 1.1081x; 1.1081x over previous
#include <cuda_runtime.h>

// SpikeLoss: loss = 0.5 * sum( (outputs - psp(target))^2 )
// psp: syn_t = 0.8*syn_{t-1} + x_t ; y_t = 0.2*syn_t
// [32,256,4,4,100], T contiguous -> 131072 rows of 100 floats.
//
// One WARP per row (R6 structure) + one-iteration software prefetch:
// next row's float4 loads issue before the current row's shuffle-scan,
// overlapping memory latency with the dependent SHFL chain.
// Lane l holds timesteps [4l,4l+3]; lanes 0..24 active. No smem/barriers
// in the hot path. Fused deterministic last-block reduction (1 launch).

#define T_STEPS   100
#define THREADS   256
#define WARPS_PB  (THREADS / 32)        // 8
#define NBLOCKS   1024
#define ROWS_PER_WARP 16                // 131072 / (1024*8)

#define A1  0.8f
#define A2  0.64f
#define A3  0.512f
#define A4  0.4096f
#define A8  0.16777216f
#define A16 0.028147497671065608f
#define A32 0.0007922816251426434f
#define A64 6.277101735386681e-07f
#define INV_TAU 0.2f

__device__ float    g_partials[NBLOCKS];
__device__ unsigned g_count = 0;

__device__ __forceinline__ float row_scan_sq(float4 x, float4 o, int lane, bool active)
{
    // Intra-lane scan of 4 timesteps
    float p0 = x.x;
    float p1 = fmaf(A1, p0, x.y);
    float p2 = fmaf(A1, p1, x.z);
    float p3 = fmaf(A1, p2, x.w);

    // Kogge-Stone inclusive scan over segment totals (ratio 0.8^4)
    float T = p3, u;
    u = __shfl_up_sync(0xFFFFFFFFu, T, 1);  if (lane >= 1)  T = fmaf(A4,  u, T);
    u = __shfl_up_sync(0xFFFFFFFFu, T, 2);  if (lane >= 2)  T = fmaf(A8,  u, T);
    u = __shfl_up_sync(0xFFFFFFFFu, T, 4);  if (lane >= 4)  T = fmaf(A16, u, T);
    u = __shfl_up_sync(0xFFFFFFFFu, T, 8);  if (lane >= 8)  T = fmaf(A32, u, T);
    u = __shfl_up_sync(0xFFFFFFFFu, T, 16); if (lane >= 16) T = fmaf(A64, u, T);

    // Exclusive carry entering this lane's segment
    float C = __shfl_up_sync(0xFFFFFFFFu, T, 1);
    if (lane == 0) C = 0.0f;

    // Reconstruct syn, diff vs outputs, sum of squares
    float s0 = fmaf(A1, C, p0);
    float s1 = fmaf(A2, C, p1);
    float s2 = fmaf(A3, C, p2);
    float s3 = fmaf(A4, C, p3);

    float r = 0.0f;
    if (active) {
        float d0 = fmaf(-INV_TAU, s0, o.x);
        float d1 = fmaf(-INV_TAU, s1, o.y);
        float d2 = fmaf(-INV_TAU, s2, o.z);
        float d3 = fmaf(-INV_TAU, s3, o.w);
        r = d0 * d0;
        r = fmaf(d1, d1, r);
        r = fmaf(d2, d2, r);
        r = fmaf(d3, d3, r);
    }
    return r;
}

__global__ void __launch_bounds__(THREADS)
spike_loss_warpscan(const float* __restrict__ outputs,
                    const float* __restrict__ target,
                    float* __restrict__ out,
                    int n_blocks)
{
    __shared__ float s_warp[WARPS_PB];
    __shared__ int   s_is_last;

    const int tid  = threadIdx.x;
    const int lane = tid & 31;
    const int wid  = tid >> 5;
    const int gwarp = blockIdx.x * WARPS_PB + wid;
    const bool active = (lane < 25);

    const float4* __restrict__ t4 = (const float4*)target;
    const float4* __restrict__ o4 = (const float4*)outputs;

    const size_t base0 = (size_t)gwarp * ROWS_PER_WARP * 25;

    float acc = 0.0f;

    // Prologue: load row 0
    float4 x = make_float4(0.f, 0.f, 0.f, 0.f);
    float4 o = x;
    if (active) {
        x = __ldcs(&t4[base0 + lane]);
        o = __ldcs(&o4[base0 + lane]);
    }

    #pragma unroll 2
    for (int i = 0; i < ROWS_PER_WARP; i++) {
        // Prefetch next row before scanning current one
        float4 xn = make_float4(0.f, 0.f, 0.f, 0.f);
        float4 on = xn;
        if (i + 1 < ROWS_PER_WARP && active) {
            size_t b = base0 + (size_t)(i + 1) * 25 + lane;
            xn = __ldcs(&t4[b]);
            on = __ldcs(&o4[b]);
        }

        acc += row_scan_sq(x, o, lane, active);

        x = xn; o = on;
    }

    // ---- Block reduction (deterministic) ----
    #pragma unroll
    for (int off = 16; off > 0; off >>= 1)
        acc += __shfl_down_sync(0xFFFFFFFFu, acc, off);
    if (lane == 0) s_warp[wid] = acc;
    __syncthreads();

    if (tid == 0) {
        float v = 0.0f;
        #pragma unroll
        for (int w = 0; w < WARPS_PB; w++) v += s_warp[w];
        g_partials[blockIdx.x] = v;
        __threadfence();
        unsigned old = atomicAdd(&g_count, 1u);
        s_is_last = (old == (unsigned)(n_blocks - 1));
    }
    __syncthreads();

    // ---- Last block: deterministic final reduce ----
    if (s_is_last) {
        float v = 0.0f;
        #pragma unroll
        for (int j = 0; j < NBLOCKS / THREADS; j++) {      // fixed order
            int idx = tid + j * THREADS;
            if (idx < n_blocks) v += g_partials[idx];
        }
        #pragma unroll
        for (int off = 16; off > 0; off >>= 1)
            v += __shfl_down_sync(0xFFFFFFFFu, v, off);
        if (lane == 0) s_warp[wid] = v;
        __syncthreads();
        if (tid == 0) {
            float r = 0.0f;
            #pragma unroll
            for (int w = 0; w < WARPS_PB; w++) r += s_warp[w];
            out[0] = 0.5f * r;
            g_count = 0;   // reset for next graph replay
        }
    }
}

extern "C" void kernel_launch(void* const* d_in, const int* in_sizes, int n_in,
                              void* d_out, int out_size)
{
    const float* outputs = (const float*)d_in[0];
    const float* target  = (const float*)d_in[1];
    float* out = (float*)d_out;

    int n_rows = in_sizes[0] / T_STEPS;                 // 131072
    int blocks = n_rows / (WARPS_PB * ROWS_PER_WARP);   // 1024

    spike_loss_warpscan<<<blocks, THREADS>>>(outputs, target, out, blocks);
}